// round 11
// baseline (speedup 1.0000x reference)
#include <cuda_runtime.h>
#include <math.h>

#define NUM_B 2
#define NUM_C 256
#define NUM_H 256
#define NUM_W 256
#define NUM_N 512
#define OUT_H 7
#define OUT_W 7
#define NBIN 49
#define HW (NUM_H * NUM_W)
#define CHW (NUM_C * HW)
#define C_HALF 128
#define SOUT_PAD 133
#define T_BLOCKS (8 * 8 * 256)   // per-batch transpose blocks
#define P_BLOCKS (NUM_N * 2)     // per-batch pool blocks (roi * 2 halves)

// NHWC copy of x: xT[b][y][x][c]
__device__ float xT_buf[(size_t)NUM_B * NUM_H * NUM_W * NUM_C];

// ---------------------------------------------------------------------------
// Transpose one 32(c) x 32(w) tile of one h-slice. 256 linear threads.
// ---------------------------------------------------------------------------
__device__ __forceinline__ void transpose_tile(const float* __restrict__ x,
                                               int b, int t, int tid)
{
    __shared__ float tile[32][33];

    const int w0 = (t & 7) * 32;
    const int c0 = ((t >> 3) & 7) * 32;
    const int h  = t >> 6;
    const int tx = tid & 7;     // float4 index along w / c
    const int ty = tid >> 3;    // 0..31

    const float* src = x + (((size_t)b * NUM_C + c0 + ty) * NUM_H + h) * NUM_W
                         + w0 + tx * 4;
    float4 v = *reinterpret_cast<const float4*>(src);
    tile[ty][tx * 4 + 0] = v.x;
    tile[ty][tx * 4 + 1] = v.y;
    tile[ty][tx * 4 + 2] = v.z;
    tile[ty][tx * 4 + 3] = v.w;
    __syncthreads();

    float4 o;
    o.x = tile[tx * 4 + 0][ty];
    o.y = tile[tx * 4 + 1][ty];
    o.z = tile[tx * 4 + 2][ty];
    o.w = tile[tx * 4 + 3][ty];
    float* dst = xT_buf + (((size_t)b * NUM_H + h) * NUM_W + w0 + ty) * NUM_C
                        + c0 + tx * 4;
    *reinterpret_cast<float4*>(dst) = o;
}

// ---------------------------------------------------------------------------
// Pool one (roi, channel-half) pair from NHWC. 256 linear threads.
// ---------------------------------------------------------------------------
__device__ __forceinline__ void pool_block(const float* __restrict__ boxes,
                                           float* __restrict__ out,
                                           int b, int blk, int tid)
{
    __shared__ int   s_pos[NBIN][4];
    __shared__ float s_wgt[NBIN][4];
    __shared__ float s_out[NBIN][SOUT_PAD];

    const int roi  = b * NUM_N + (blk >> 1);
    const int half = blk & 1;

    if (tid < NBIN) {
        const float* bx = boxes + roi * 5;
        float cx  = __fmul_rn(bx[0], 0.25f);
        float cy  = __fmul_rn(bx[1], 0.25f);
        float w   = __fmul_rn(bx[2], 0.25f);
        float h   = __fmul_rn(bx[3], 0.25f);
        float ang = __fmul_rn(bx[4], 0.017453292519943295f);

        float Sx = __fdiv_rn(w, 7.0f);
        float Sy = __fdiv_rn(h, 7.0f);
        float ca = cosf(ang);
        float sa = sinf(ang);

        const float dxc = -3.5f;
        const float dyc = -3.5f;

        float M00 = __fmul_rn(ca, Sx);
        float M01 = __fmul_rn(sa, Sy);
        float M02 = __fadd_rn(__fadd_rn(__fmul_rn(__fmul_rn(ca, Sx), dxc),
                                        __fmul_rn(__fmul_rn(sa, Sy), dyc)), cx);
        float M10 = __fmul_rn(-sa, Sx);
        float M11 = __fmul_rn(ca, Sy);
        float M12 = __fadd_rn(__fadd_rn(__fmul_rn(__fmul_rn(-sa, Sx), dxc),
                                        __fmul_rn(__fmul_rn(ca, Sy), dyc)), cy);

        int ph = tid / OUT_W;
        int pw = tid - ph * OUT_W;

        const float offx[4] = {0.f, 0.f, 1.f, 1.f};
        const float offy[4] = {0.f, 1.f, 0.f, 1.f};

        float minX =  3.0e38f, maxX = -3.0e38f;
        float minY =  3.0e38f, maxY = -3.0e38f;
        #pragma unroll
        for (int k = 0; k < 4; ++k) {
            float pwc = (float)pw + offx[k];
            float phc = (float)ph + offy[k];
            float X = __fadd_rn(__fadd_rn(__fmul_rn(M00, pwc), __fmul_rn(M01, phc)), M02);
            float Y = __fadd_rn(__fadd_rn(__fmul_rn(M10, pwc), __fmul_rn(M11, phc)), M12);
            minX = fminf(minX, X); maxX = fmaxf(maxX, X);
            minY = fminf(minY, Y); maxY = fmaxf(maxY, Y);
        }

        float lM = fmaxf(rintf(minX), 0.0f);
        float rM = fminf(rintf(maxX), (float)(NUM_W - 1));
        float tM = fmaxf(rintf(minY), 0.0f);
        float bM = fminf(rintf(maxY), (float)(NUM_H - 1));

        float bcx = __fmul_rn(__fadd_rn(lM, rM), 0.5f);
        float bcy = __fmul_rn(__fadd_rn(tM, bM), 0.5f);

        float flx = floorf(bcx);
        float fly = floorf(bcy);
        int il = (int)flx;
        int it = (int)fly;
        int ir = (int)ceilf(bcx);
        int ib = (int)ceilf(bcy);
        float rx = __fsub_rn(bcx, flx);
        float ry = __fsub_rn(bcy, fly);

        float omrx = __fsub_rn(1.0f, rx);
        float omry = __fsub_rn(1.0f, ry);
        float wlt = __fmul_rn(omrx, omry);
        float wrt = __fmul_rn(rx,   omry);
        float wrb = __fmul_rn(rx,   ry);
        float wlb = __fmul_rn(omrx, ry);

        bool vl = (il >= 0) && (il < NUM_W);
        bool vr = (ir >= 0) && (ir < NUM_W);
        bool vt = (it >= 0) && (it < NUM_H);
        bool vb = (ib >= 0) && (ib < NUM_H);

        int cl = min(max(il, 0), NUM_W - 1);
        int cr = min(max(ir, 0), NUM_W - 1);
        int ct = min(max(it, 0), NUM_H - 1);
        int cb = min(max(ib, 0), NUM_H - 1);

        s_pos[tid][0] = ct * NUM_W + cl;
        s_pos[tid][1] = ct * NUM_W + cr;
        s_pos[tid][2] = cb * NUM_W + cr;
        s_pos[tid][3] = cb * NUM_W + cl;

        s_wgt[tid][0] = (vt && vl) ? wlt : 0.0f;
        s_wgt[tid][1] = (vt && vr) ? wrt : 0.0f;
        s_wgt[tid][2] = (vb && vr) ? wrb : 0.0f;
        s_wgt[tid][3] = (vb && vl) ? wlb : 0.0f;
    }
    __syncthreads();

    const int wid  = tid >> 5;
    const int lane = tid & 31;

    const float* base = xT_buf + ((size_t)b * HW * NUM_C)
                      + half * C_HALF + lane * 4;

    for (int bin = wid; bin < NBIN; bin += 8) {
        float4 acc = make_float4(0.f, 0.f, 0.f, 0.f);
        #pragma unroll
        for (int k = 0; k < 4; ++k) {
            float wgt = s_wgt[bin][k];          // warp-uniform
            if (wgt != 0.0f) {
                float4 v = *reinterpret_cast<const float4*>(
                    base + (size_t)s_pos[bin][k] * NUM_C);
                acc.x += v.x * wgt;
                acc.y += v.y * wgt;
                acc.z += v.z * wgt;
                acc.w += v.w * wgt;
            }
        }
        s_out[bin][lane * 4 + 0] = fmaxf(acc.x, 0.0f);
        s_out[bin][lane * 4 + 1] = fmaxf(acc.y, 0.0f);
        s_out[bin][lane * 4 + 2] = fmaxf(acc.z, 0.0f);
        s_out[bin][lane * 4 + 3] = fmaxf(acc.w, 0.0f);
    }
    __syncthreads();

    float* ob = out + (size_t)roi * (NUM_C * NBIN) + (size_t)half * C_HALF * NBIN;
    for (int i = tid; i < C_HALF * NBIN; i += 256) {
        int c   = i / NBIN;
        int bin = i - c * NBIN;
        ob[i] = s_out[bin][c];
    }
}

// ---------------------------------------------------------------------------
// Kernels
// ---------------------------------------------------------------------------
__global__ __launch_bounds__(256) void k_transpose(const float* __restrict__ x, int b)
{
    transpose_tile(x, b, blockIdx.x, threadIdx.x);
}

// Fused: pool batch 0 (blocks 0..P_BLOCKS-1, scheduled first) + transpose batch 1.
__global__ __launch_bounds__(256) void k_fused(const float* __restrict__ x,
                                               const float* __restrict__ boxes,
                                               float* __restrict__ out)
{
    if (blockIdx.x < P_BLOCKS) {
        pool_block(boxes, out, 0, blockIdx.x, threadIdx.x);
    } else {
        transpose_tile(x, 1, blockIdx.x - P_BLOCKS, threadIdx.x);
    }
}

__global__ __launch_bounds__(256) void k_pool(const float* __restrict__ boxes,
                                              float* __restrict__ out, int b)
{
    pool_block(boxes, out, b, blockIdx.x, threadIdx.x);
}

extern "C" void kernel_launch(void* const* d_in, const int* in_sizes, int n_in,
                              void* d_out, int out_size) {
    const float* x     = (const float*)d_in[0];   // (2,256,256,256) f32
    const float* boxes = (const float*)d_in[1];   // (2,512,5) f32
    float* out = (float*)d_out;                   // (1024,256,7,7) f32
    (void)in_sizes; (void)n_in; (void)out_size;

    k_transpose<<<T_BLOCKS, 256>>>(x, 0);                 // T0
    k_fused<<<P_BLOCKS + T_BLOCKS, 256>>>(x, boxes, out); // P0 ∥ T1
    k_pool<<<P_BLOCKS, 256>>>(boxes, out, 1);             // P1
}

// round 12
// speedup vs baseline: 1.1999x; 1.1999x over previous
#include <cuda_runtime.h>
#include <cuda_fp16.h>
#include <math.h>

#define NUM_B 2
#define NUM_C 256
#define NUM_H 256
#define NUM_W 256
#define NUM_N 512
#define OUT_H 7
#define OUT_W 7
#define NBIN 49
#define HW (NUM_H * NUM_W)
#define CHW (NUM_C * HW)
#define C_HALF 128
#define SOUT_PAD 133

// fp16 NHWC copy of x: xT[b][y][x][c]  (64 MB total)
__device__ __half xT_buf[(size_t)NUM_B * NUM_H * NUM_W * NUM_C];

// ---------------------------------------------------------------------------
// Kernel A: NCHW fp32 -> NHWC fp16 transpose.
// grid (W/32, C/32, B*H), block (8, 32). Thread: 1 float4 in, 4 halfs out.
// ---------------------------------------------------------------------------
__global__ __launch_bounds__(256) void transpose_kernel(const float* __restrict__ x)
{
    __shared__ float tile[32][33];

    const int w0 = blockIdx.x * 32;
    const int c0 = blockIdx.y * 32;
    const int bh = blockIdx.z;           // b*256 + h
    const int b  = bh >> 8;
    const int h  = bh & 255;
    const int tx = threadIdx.x;          // 0..7
    const int ty = threadIdx.y;          // 0..31

    // load: channel = c0+ty, 4 consecutive w. Coalesced LDG.128.
    const float* src = x + (((size_t)b * NUM_C + c0 + ty) * NUM_H + h) * NUM_W
                         + w0 + tx * 4;
    float4 v = *reinterpret_cast<const float4*>(src);
    tile[ty][tx * 4 + 0] = v.x;
    tile[ty][tx * 4 + 1] = v.y;
    tile[ty][tx * 4 + 2] = v.z;
    tile[ty][tx * 4 + 3] = v.w;
    __syncthreads();

    // store: w = w0+ty, 4 consecutive channels as fp16 (8B store).
    __half2 lo = __floats2half2_rn(tile[tx * 4 + 0][ty], tile[tx * 4 + 1][ty]);
    __half2 hi = __floats2half2_rn(tile[tx * 4 + 2][ty], tile[tx * 4 + 3][ty]);
    uint2 pak;
    pak.x = *reinterpret_cast<unsigned int*>(&lo);
    pak.y = *reinterpret_cast<unsigned int*>(&hi);

    __half* dst = xT_buf + (((size_t)b * NUM_H + h) * NUM_W + w0 + ty) * NUM_C
                         + c0 + tx * 4;
    *reinterpret_cast<uint2*>(dst) = pak;
}

// ---------------------------------------------------------------------------
// Kernel B: RROI pool from fp16 NHWC. grid = 2048 (roi * 2 halves), block 256.
// ---------------------------------------------------------------------------
__global__ __launch_bounds__(256) void rroi_pool_kernel(
    const float* __restrict__ boxes,
    float* __restrict__ out)
{
    __shared__ int   s_pos[NBIN][4];        // clamped corner spatial idx y*256+x
    __shared__ float s_wgt[NBIN][4];        // validity-folded weights lt,rt,rb,lb
    __shared__ float s_out[NBIN][SOUT_PAD]; // [bin][channel-within-half]

    const int roi  = blockIdx.x >> 1;
    const int half = blockIdx.x & 1;
    const int tid  = threadIdx.x;

    if (tid < NBIN) {
        const float* bx = boxes + roi * 5;
        float cx  = __fmul_rn(bx[0], 0.25f);
        float cy  = __fmul_rn(bx[1], 0.25f);
        float w   = __fmul_rn(bx[2], 0.25f);
        float h   = __fmul_rn(bx[3], 0.25f);
        float ang = __fmul_rn(bx[4], 0.017453292519943295f);

        float Sx = __fdiv_rn(w, 7.0f);
        float Sy = __fdiv_rn(h, 7.0f);
        float ca = cosf(ang);
        float sa = sinf(ang);

        const float dxc = -3.5f;
        const float dyc = -3.5f;

        float M00 = __fmul_rn(ca, Sx);
        float M01 = __fmul_rn(sa, Sy);
        float M02 = __fadd_rn(__fadd_rn(__fmul_rn(__fmul_rn(ca, Sx), dxc),
                                        __fmul_rn(__fmul_rn(sa, Sy), dyc)), cx);
        float M10 = __fmul_rn(-sa, Sx);
        float M11 = __fmul_rn(ca, Sy);
        float M12 = __fadd_rn(__fadd_rn(__fmul_rn(__fmul_rn(-sa, Sx), dxc),
                                        __fmul_rn(__fmul_rn(ca, Sy), dyc)), cy);

        int ph = tid / OUT_W;
        int pw = tid - ph * OUT_W;

        const float offx[4] = {0.f, 0.f, 1.f, 1.f};
        const float offy[4] = {0.f, 1.f, 0.f, 1.f};

        float minX =  3.0e38f, maxX = -3.0e38f;
        float minY =  3.0e38f, maxY = -3.0e38f;
        #pragma unroll
        for (int k = 0; k < 4; ++k) {
            float pwc = (float)pw + offx[k];
            float phc = (float)ph + offy[k];
            float X = __fadd_rn(__fadd_rn(__fmul_rn(M00, pwc), __fmul_rn(M01, phc)), M02);
            float Y = __fadd_rn(__fadd_rn(__fmul_rn(M10, pwc), __fmul_rn(M11, phc)), M12);
            minX = fminf(minX, X); maxX = fmaxf(maxX, X);
            minY = fminf(minY, Y); maxY = fmaxf(maxY, Y);
        }

        float lM = fmaxf(rintf(minX), 0.0f);
        float rM = fminf(rintf(maxX), (float)(NUM_W - 1));
        float tM = fmaxf(rintf(minY), 0.0f);
        float bM = fminf(rintf(maxY), (float)(NUM_H - 1));

        float bcx = __fmul_rn(__fadd_rn(lM, rM), 0.5f);
        float bcy = __fmul_rn(__fadd_rn(tM, bM), 0.5f);

        float flx = floorf(bcx);
        float fly = floorf(bcy);
        int il = (int)flx;
        int it = (int)fly;
        int ir = (int)ceilf(bcx);
        int ib = (int)ceilf(bcy);
        float rx = __fsub_rn(bcx, flx);
        float ry = __fsub_rn(bcy, fly);

        float omrx = __fsub_rn(1.0f, rx);
        float omry = __fsub_rn(1.0f, ry);
        float wlt = __fmul_rn(omrx, omry);
        float wrt = __fmul_rn(rx,   omry);
        float wrb = __fmul_rn(rx,   ry);
        float wlb = __fmul_rn(omrx, ry);

        bool vl = (il >= 0) && (il < NUM_W);
        bool vr = (ir >= 0) && (ir < NUM_W);
        bool vt = (it >= 0) && (it < NUM_H);
        bool vb = (ib >= 0) && (ib < NUM_H);

        int cl = min(max(il, 0), NUM_W - 1);
        int cr = min(max(ir, 0), NUM_W - 1);
        int ct = min(max(it, 0), NUM_H - 1);
        int cb = min(max(ib, 0), NUM_H - 1);

        s_pos[tid][0] = ct * NUM_W + cl;
        s_pos[tid][1] = ct * NUM_W + cr;
        s_pos[tid][2] = cb * NUM_W + cr;
        s_pos[tid][3] = cb * NUM_W + cl;

        s_wgt[tid][0] = (vt && vl) ? wlt : 0.0f;
        s_wgt[tid][1] = (vt && vr) ? wrt : 0.0f;
        s_wgt[tid][2] = (vb && vr) ? wrb : 0.0f;
        s_wgt[tid][3] = (vb && vl) ? wlb : 0.0f;
    }
    __syncthreads();

    const int wid  = tid >> 5;
    const int lane = tid & 31;

    // base: xT[b][.][.][half*128 + lane*4]  (fp16)
    const __half* base = xT_buf + ((size_t)(roi >> 9) * HW * NUM_C)
                       + half * C_HALF + lane * 4;

    for (int bin = wid; bin < NBIN; bin += 8) {
        float4 acc = make_float4(0.f, 0.f, 0.f, 0.f);
        #pragma unroll
        for (int k = 0; k < 4; ++k) {
            float wgt = s_wgt[bin][k];          // warp-uniform
            if (wgt != 0.0f) {
                uint2 pak = *reinterpret_cast<const uint2*>(
                    base + (size_t)s_pos[bin][k] * NUM_C);
                __half2 h0 = *reinterpret_cast<__half2*>(&pak.x);
                __half2 h1 = *reinterpret_cast<__half2*>(&pak.y);
                float2 f0 = __half22float2(h0);
                float2 f1 = __half22float2(h1);
                acc.x += f0.x * wgt;
                acc.y += f0.y * wgt;
                acc.z += f1.x * wgt;
                acc.w += f1.y * wgt;
            }
        }
        s_out[bin][lane * 4 + 0] = fmaxf(acc.x, 0.0f);
        s_out[bin][lane * 4 + 1] = fmaxf(acc.y, 0.0f);
        s_out[bin][lane * 4 + 2] = fmaxf(acc.z, 0.0f);
        s_out[bin][lane * 4 + 3] = fmaxf(acc.w, 0.0f);
    }
    __syncthreads();

    // Coalesced write-out: 128 channels x 49 bins = 6272 floats per block.
    float* ob = out + (size_t)roi * (NUM_C * NBIN) + (size_t)half * C_HALF * NBIN;
    for (int i = tid; i < C_HALF * NBIN; i += 256) {
        int c   = i / NBIN;
        int bin = i - c * NBIN;
        ob[i] = s_out[bin][c];
    }
}

extern "C" void kernel_launch(void* const* d_in, const int* in_sizes, int n_in,
                              void* d_out, int out_size) {
    const float* x     = (const float*)d_in[0];   // (2,256,256,256) f32
    const float* boxes = (const float*)d_in[1];   // (2,512,5) f32
    float* out = (float*)d_out;                   // (1024,256,7,7) f32
    (void)in_sizes; (void)n_in; (void)out_size;

    dim3 tgrid(NUM_W / 32, NUM_C / 32, NUM_B * NUM_H);
    dim3 tblk(8, 32);
    transpose_kernel<<<tgrid, tblk>>>(x);

    rroi_pool_kernel<<<NUM_B * NUM_N * 2, 256>>>(boxes, out);
}

// round 13
// speedup vs baseline: 1.4465x; 1.2055x over previous
#include <cuda_runtime.h>
#include <cuda_fp16.h>
#include <math.h>

#define NUM_B 2
#define NUM_C 256
#define NUM_H 256
#define NUM_W 256
#define NUM_N 512
#define OUT_H 7
#define OUT_W 7
#define NBIN 49
#define HW (NUM_H * NUM_W)
#define CHW (NUM_C * HW)
#define C_HALF 128
#define SOUT_PAD 133

// fp16 NHWC copy of x: xT[b][y][x][c]  (64 MB total)
__device__ __half xT_buf[(size_t)NUM_B * NUM_H * NUM_W * NUM_C];

// ---------------------------------------------------------------------------
// Kernel A: NCHW fp32 -> NHWC fp16 transpose, 4 h-slices per block.
// grid (W/32, C/32, B*H/4), block (8, 32). Thread: 4 independent LDG.128.
// ---------------------------------------------------------------------------
__global__ __launch_bounds__(256) void transpose_kernel(const float* __restrict__ x)
{
    __shared__ float tile[4][32][33];

    const int w0 = blockIdx.x * 32;
    const int c0 = blockIdx.y * 32;
    const int z  = blockIdx.z;           // b*64 + h/4
    const int b  = z >> 6;
    const int h0 = (z & 63) * 4;
    const int tx = threadIdx.x;          // 0..7
    const int ty = threadIdx.y;          // 0..31

    // 4 independent coalesced LDG.128 (different h-slices), front-batched.
    const float* src = x + (((size_t)b * NUM_C + c0 + ty) * NUM_H + h0) * NUM_W
                         + w0 + tx * 4;
    float4 v[4];
    #pragma unroll
    for (int k = 0; k < 4; ++k)
        v[k] = *reinterpret_cast<const float4*>(src + (size_t)k * NUM_W);

    #pragma unroll
    for (int k = 0; k < 4; ++k) {
        tile[k][ty][tx * 4 + 0] = v[k].x;
        tile[k][ty][tx * 4 + 1] = v[k].y;
        tile[k][ty][tx * 4 + 2] = v[k].z;
        tile[k][ty][tx * 4 + 3] = v[k].w;
    }
    __syncthreads();

    // 4 independent 8B stores: w = w0+ty, 4 consecutive channels as fp16.
    #pragma unroll
    for (int k = 0; k < 4; ++k) {
        __half2 lo = __floats2half2_rn(tile[k][tx * 4 + 0][ty], tile[k][tx * 4 + 1][ty]);
        __half2 hi = __floats2half2_rn(tile[k][tx * 4 + 2][ty], tile[k][tx * 4 + 3][ty]);
        uint2 pak;
        pak.x = *reinterpret_cast<unsigned int*>(&lo);
        pak.y = *reinterpret_cast<unsigned int*>(&hi);

        __half* dst = xT_buf + (((size_t)b * NUM_H + h0 + k) * NUM_W + w0 + ty) * NUM_C
                             + c0 + tx * 4;
        *reinterpret_cast<uint2*>(dst) = pak;
    }
}

// ---------------------------------------------------------------------------
// Kernel B: RROI pool from fp16 NHWC. grid = 2048 (roi * 2 halves), block 256.
// ---------------------------------------------------------------------------
__global__ __launch_bounds__(256) void rroi_pool_kernel(
    const float* __restrict__ boxes,
    float* __restrict__ out)
{
    __shared__ int   s_pos[NBIN][4];        // clamped corner spatial idx y*256+x
    __shared__ float s_wgt[NBIN][4];        // validity-folded weights lt,rt,rb,lb
    __shared__ float s_out[NBIN][SOUT_PAD]; // [bin][channel-within-half]

    const int roi  = blockIdx.x >> 1;
    const int half = blockIdx.x & 1;
    const int tid  = threadIdx.x;

    if (tid < NBIN) {
        const float* bx = boxes + roi * 5;
        float cx  = __fmul_rn(bx[0], 0.25f);
        float cy  = __fmul_rn(bx[1], 0.25f);
        float w   = __fmul_rn(bx[2], 0.25f);
        float h   = __fmul_rn(bx[3], 0.25f);
        float ang = __fmul_rn(bx[4], 0.017453292519943295f);

        float Sx = __fdiv_rn(w, 7.0f);
        float Sy = __fdiv_rn(h, 7.0f);
        float ca = cosf(ang);
        float sa = sinf(ang);

        const float dxc = -3.5f;
        const float dyc = -3.5f;

        float M00 = __fmul_rn(ca, Sx);
        float M01 = __fmul_rn(sa, Sy);
        float M02 = __fadd_rn(__fadd_rn(__fmul_rn(__fmul_rn(ca, Sx), dxc),
                                        __fmul_rn(__fmul_rn(sa, Sy), dyc)), cx);
        float M10 = __fmul_rn(-sa, Sx);
        float M11 = __fmul_rn(ca, Sy);
        float M12 = __fadd_rn(__fadd_rn(__fmul_rn(__fmul_rn(-sa, Sx), dxc),
                                        __fmul_rn(__fmul_rn(ca, Sy), dyc)), cy);

        int ph = tid / OUT_W;
        int pw = tid - ph * OUT_W;

        const float offx[4] = {0.f, 0.f, 1.f, 1.f};
        const float offy[4] = {0.f, 1.f, 0.f, 1.f};

        float minX =  3.0e38f, maxX = -3.0e38f;
        float minY =  3.0e38f, maxY = -3.0e38f;
        #pragma unroll
        for (int k = 0; k < 4; ++k) {
            float pwc = (float)pw + offx[k];
            float phc = (float)ph + offy[k];
            float X = __fadd_rn(__fadd_rn(__fmul_rn(M00, pwc), __fmul_rn(M01, phc)), M02);
            float Y = __fadd_rn(__fadd_rn(__fmul_rn(M10, pwc), __fmul_rn(M11, phc)), M12);
            minX = fminf(minX, X); maxX = fmaxf(maxX, X);
            minY = fminf(minY, Y); maxY = fmaxf(maxY, Y);
        }

        float lM = fmaxf(rintf(minX), 0.0f);
        float rM = fminf(rintf(maxX), (float)(NUM_W - 1));
        float tM = fmaxf(rintf(minY), 0.0f);
        float bM = fminf(rintf(maxY), (float)(NUM_H - 1));

        float bcx = __fmul_rn(__fadd_rn(lM, rM), 0.5f);
        float bcy = __fmul_rn(__fadd_rn(tM, bM), 0.5f);

        float flx = floorf(bcx);
        float fly = floorf(bcy);
        int il = (int)flx;
        int it = (int)fly;
        int ir = (int)ceilf(bcx);
        int ib = (int)ceilf(bcy);
        float rx = __fsub_rn(bcx, flx);
        float ry = __fsub_rn(bcy, fly);

        float omrx = __fsub_rn(1.0f, rx);
        float omry = __fsub_rn(1.0f, ry);
        float wlt = __fmul_rn(omrx, omry);
        float wrt = __fmul_rn(rx,   omry);
        float wrb = __fmul_rn(rx,   ry);
        float wlb = __fmul_rn(omrx, ry);

        bool vl = (il >= 0) && (il < NUM_W);
        bool vr = (ir >= 0) && (ir < NUM_W);
        bool vt = (it >= 0) && (it < NUM_H);
        bool vb = (ib >= 0) && (ib < NUM_H);

        int cl = min(max(il, 0), NUM_W - 1);
        int cr = min(max(ir, 0), NUM_W - 1);
        int ct = min(max(it, 0), NUM_H - 1);
        int cb = min(max(ib, 0), NUM_H - 1);

        s_pos[tid][0] = ct * NUM_W + cl;
        s_pos[tid][1] = ct * NUM_W + cr;
        s_pos[tid][2] = cb * NUM_W + cr;
        s_pos[tid][3] = cb * NUM_W + cl;

        s_wgt[tid][0] = (vt && vl) ? wlt : 0.0f;
        s_wgt[tid][1] = (vt && vr) ? wrt : 0.0f;
        s_wgt[tid][2] = (vb && vr) ? wrb : 0.0f;
        s_wgt[tid][3] = (vb && vl) ? wlb : 0.0f;
    }
    __syncthreads();

    const int wid  = tid >> 5;
    const int lane = tid & 31;

    // base: xT[b][.][.][half*128 + lane*4]  (fp16)
    const __half* base = xT_buf + ((size_t)(roi >> 9) * HW * NUM_C)
                       + half * C_HALF + lane * 4;

    for (int bin = wid; bin < NBIN; bin += 8) {
        float4 acc = make_float4(0.f, 0.f, 0.f, 0.f);
        #pragma unroll
        for (int k = 0; k < 4; ++k) {
            float wgt = s_wgt[bin][k];          // warp-uniform
            if (wgt != 0.0f) {
                uint2 pak = *reinterpret_cast<const uint2*>(
                    base + (size_t)s_pos[bin][k] * NUM_C);
                __half2 h0 = *reinterpret_cast<__half2*>(&pak.x);
                __half2 h1 = *reinterpret_cast<__half2*>(&pak.y);
                float2 f0 = __half22float2(h0);
                float2 f1 = __half22float2(h1);
                acc.x += f0.x * wgt;
                acc.y += f0.y * wgt;
                acc.z += f1.x * wgt;
                acc.w += f1.y * wgt;
            }
        }
        s_out[bin][lane * 4 + 0] = fmaxf(acc.x, 0.0f);
        s_out[bin][lane * 4 + 1] = fmaxf(acc.y, 0.0f);
        s_out[bin][lane * 4 + 2] = fmaxf(acc.z, 0.0f);
        s_out[bin][lane * 4 + 3] = fmaxf(acc.w, 0.0f);
    }
    __syncthreads();

    // Coalesced write-out: 128 channels x 49 bins = 6272 floats per block.
    float* ob = out + (size_t)roi * (NUM_C * NBIN) + (size_t)half * C_HALF * NBIN;
    for (int i = tid; i < C_HALF * NBIN; i += 256) {
        int c   = i / NBIN;
        int bin = i - c * NBIN;
        ob[i] = s_out[bin][c];
    }
}

extern "C" void kernel_launch(void* const* d_in, const int* in_sizes, int n_in,
                              void* d_out, int out_size) {
    const float* x     = (const float*)d_in[0];   // (2,256,256,256) f32
    const float* boxes = (const float*)d_in[1];   // (2,512,5) f32
    float* out = (float*)d_out;                   // (1024,256,7,7) f32
    (void)in_sizes; (void)n_in; (void)out_size;

    dim3 tgrid(NUM_W / 32, NUM_C / 32, NUM_B * NUM_H / 4);
    dim3 tblk(8, 32);
    transpose_kernel<<<tgrid, tblk>>>(x);

    rroi_pool_kernel<<<NUM_B * NUM_N * 2, 256>>>(boxes, out);
}